// round 6
// baseline (speedup 1.0000x reference)
#include <cuda_runtime.h>
#include <cstdint>
#include <cstddef>

#define NEGV (-1e30f)

static const int Bn = 128;
static const int Tn = 2048;
static const int Nn = 64;
static const int Ln = 256;

// result scratch (device globals: allocation-free)
__device__ float g_fcc[Bn];
__device__ float g_fac[Bn];

// ---------------------------------------------------------------------------
// Packed f32x2 helpers (Blackwell: fma.rn.f32x2 only reachable via PTX)
// ---------------------------------------------------------------------------
__device__ __forceinline__ void fma2(unsigned long long& acc,
                                     unsigned long long e,
                                     unsigned long long w) {
    asm("fma.rn.f32x2 %0, %1, %2, %0;" : "+l"(acc) : "l"(e), "l"(w));
}
__device__ __forceinline__ unsigned long long add2(unsigned long long a,
                                                   unsigned long long b) {
    unsigned long long r;
    asm("add.rn.f32x2 %0, %1, %2;" : "=l"(r) : "l"(a), "l"(b));
    return r;
}
__device__ __forceinline__ float frcp(float x) {
    float r;
    asm("rcp.approx.f32 %0, %1;" : "=f"(r) : "f"(x));
    return r;
}
__device__ __forceinline__ void cp16(void* dst, const void* src) {
    unsigned int d = (unsigned int)__cvta_generic_to_shared(dst);
    asm volatile("cp.async.cg.shared.global [%0], [%1], 16;" :: "r"(d), "l"(src) : "memory");
}
#define CP_COMMIT() asm volatile("cp.async.commit_group;" ::: "memory")
#define CP_WAIT3()  asm volatile("cp.async.wait_group 3;" ::: "memory")

// ---------------------------------------------------------------------------
// Main kernel, grid 256 x 128 threads.
//   blocks   0..127 : fcc for batch b (64 live threads, thread = class n)
//   blocks 128..255 : fac for batch b (128 threads, thread = 2 target lanes)
// x_t staging: ring of 8 chunks x 4 rows (1KB each), one 16B cp.async per
// loader thread per 4 steps; wait+commit at chunk boundary (t&3)==3, made
// visible to all warps by the end-of-step barrier.
// ---------------------------------------------------------------------------
__global__ void __launch_bounds__(128, 1) asg_main(
    const float* __restrict__ xin_all, const int* __restrict__ tgt_all,
    const int* __restrict__ tsz_all, const float* __restrict__ trans)
{
    __shared__ __align__(16) float sx4[8][4][64]; // 8KB staging ring
    __shared__ __align__(16) float sE[2][64];     // fcc state, double buffered
    __shared__ float sfb[2][4];                   // fac warp-boundary, dbl buf

    const int role = blockIdx.x >> 7;             // 0: fcc, 1: fac
    const int b = blockIdx.x & 127;
    const int tid = threadIdx.x;
    const float* xin = xin_all + (size_t)b * Tn * Nn;

    if (role == 0) {
        // ================= fcc: scaled-exp forward scan ====================
        if (tid >= 64) return;                    // 2-warp CTA
        const int n = tid;

        unsigned long long w2[32];                // exp(trans[n, :]) packed
        const float* wr = trans + n * Nn;
#pragma unroll
        for (int j = 0; j < 32; j++) {
            float wa = __expf(wr[2 * j]);
            float wb = __expf(wr[2 * j + 1]);
            asm("mov.b64 %0, {%1, %2};" : "=l"(w2[j]) : "f"(wa), "f"(wb));
        }
        sE[0][n] = __expf(xin[n]);                // alpha0 = x0, c = 0
        float c = 0.f;

        // prologue: stage chunks 0..3 (rows 0..15)
#pragma unroll
        for (int cc = 0; cc < 4; cc++) {
            cp16(&sx4[cc][0][0] + 4 * n, xin + (size_t)cc * 256 + 4 * n);
            CP_COMMIT();
        }
        CP_WAIT3();
        __syncthreads();

        for (int t = 1; t < Tn; ++t) {
            const int slot = (t >> 2) & 7;
            const int row = t & 3;
            const int rb = (t + 1) & 1;           // E read buffer
            const int wbuf = t & 1;               // E write buffer

            const ulonglong2* ep = reinterpret_cast<const ulonglong2*>(sE[rb]);
            float e0 = sE[rb][0];                 // scalar broadcast LDS
            float rcp_e0 = frcp(e0);              // off the S critical path
            float xv = sx4[slot][row][n];
            float exp_xv = __expf(xv);            // off the S critical path

            unsigned long long acc0 = 0ull, acc1 = 0ull, acc2 = 0ull, acc3 = 0ull;
#pragma unroll
            for (int k = 0; k < 16; k++) {
                ulonglong2 e = ep[k];             // broadcast LDS.128
                if (k & 1) {
                    fma2(acc2, e.x, w2[2 * k]);
                    fma2(acc3, e.y, w2[2 * k + 1]);
                } else {
                    fma2(acc0, e.x, w2[2 * k]);
                    fma2(acc1, e.y, w2[2 * k + 1]);
                }
            }
            unsigned long long s = add2(add2(acc0, acc1), add2(acc2, acc3));
            float slo, shi;
            asm("mov.b64 {%0, %1}, %2;" : "=f"(slo), "=f"(shi) : "l"(s));
            float S = slo + shi;

            float En = S * exp_xv * rcp_e0;       // E' = S * exp(x) / E_prev[0]
            c += __logf(e0);                      // identical in all threads
            sE[wbuf][n] = En;

            if ((t & 3) == 3) {                   // ring maintenance, 1-in-4
                int nc = (t >> 2) + 4;
                if (nc < 512)
                    cp16(&sx4[nc & 7][0][0] + 4 * n, xin + (size_t)nc * 256 + 4 * n);
                CP_COMMIT();
                CP_WAIT3();
            }
            __syncthreads();
        }

        // epilogue: fcc = c + ln(sum_n E[n]);  last write buffer = 2047&1 = 1
        if (tid < 32) {
            float v = sE[1][tid] + sE[1][tid + 32];
#pragma unroll
            for (int o = 16; o > 0; o >>= 1)
                v += __shfl_xor_sync(0xffffffffu, v, o);
            if (tid == 0) g_fcc[b] = c + __logf(v);
        }
    } else {
        // ================= fac: log-domain constrained scan ================
        const int f = tid;                        // 0..127, lanes 2f, 2f+1
        const int l0 = 2 * f, l1 = 2 * f + 1;
        const int tg0 = tgt_all[b * Ln + l0];
        const int tg1 = tgt_all[b * Ln + l1];
        const int tgm = (l0 > 0) ? tgt_all[b * Ln + l0 - 1] : 0;
        const float ts0 = trans[tg0 * Nn + tg0];
        const float ts1 = trans[tg1 * Nn + tg1];
        const float tm0 = trans[tg0 * Nn + tgm];  // move into l0 (unused if l0==0)
        const float tm1 = trans[tg1 * Nn + tg0];  // move into l1
        const int tssel = tsz_all[b];

        float a0 = (l0 == 0) ? xin[tg0] : NEGV;   // alpha0[0] = x0[target[0]]
        float a1 = NEGV;
        if ((f & 31) == 31) sfb[0][f >> 5] = a1;

        if (f < 64) {
#pragma unroll
            for (int cc = 0; cc < 4; cc++) {
                cp16(&sx4[cc][0][0] + 4 * f, xin + (size_t)cc * 256 + 4 * f);
                CP_COMMIT();
            }
            CP_WAIT3();
        }
        __syncthreads();

        for (int t = 1; t < Tn; ++t) {
            const int slot = (t >> 2) & 7;
            const int row = t & 3;
            const int rb = (t + 1) & 1;
            const int wbuf = t & 1;

            // issue the neighbor exchange + emission gathers first
            float ap = __shfl_up_sync(0xffffffffu, a1, 1);
            float e0 = sx4[slot][row][tg0];
            float e1 = sx4[slot][row][tg1];
            if ((f & 31) == 0) ap = (f == 0) ? NEGV : sfb[rb][(f >> 5) - 1];

            float st1 = a1 + ts1, mv1 = a0 + tm1; // uses OLD a0
            float h1 = fmaxf(st1, mv1), lo1 = fminf(st1, mv1);
            float na1 = e1 + h1 + __logf(1.0f + __expf(lo1 - h1));

            float st0 = a0 + ts0, mv0 = ap + tm0;
            float h0 = fmaxf(st0, mv0), lo0 = fminf(st0, mv0);
            float na0 = e0 + h0 + __logf(1.0f + __expf(lo0 - h0));

            a0 = na0; a1 = na1;
            if ((f & 31) == 31) sfb[wbuf][f >> 5] = a1;

            if ((t & 3) == 3 && f < 64) {         // ring maintenance, 1-in-4
                int nc = (t >> 2) + 4;
                if (nc < 512)
                    cp16(&sx4[nc & 7][0][0] + 4 * f, xin + (size_t)nc * 256 + 4 * f);
                CP_COMMIT();
                CP_WAIT3();
            }
            __syncthreads();
        }

        if (l0 == tssel - 1) g_fac[b] = a0;
        if (l1 == tssel - 1) g_fac[b] = a1;
    }
}

// ---------------------------------------------------------------------------
__global__ void __launch_bounds__(128) combine_kernel(float* __restrict__ out) {
    int i = threadIdx.x;
    out[i] = g_fcc[i] - g_fac[i];
}

// ---------------------------------------------------------------------------
extern "C" void kernel_launch(void* const* d_in, const int* in_sizes, int n_in,
                              void* d_out, int out_size) {
    const float* in    = (const float*)d_in[0];   // input  [B,T,N] f32
    const int*   tgt   = (const int*)  d_in[1];   // target [B,L]   i32
    const int*   tsz   = (const int*)  d_in[2];   // target_size [B]
    const float* trans = (const float*)d_in[3];   // trans  [N,N]   f32
    float* out = (float*)d_out;
    (void)in_sizes; (void)n_in; (void)out_size;

    asg_main<<<2 * Bn, 128>>>(in, tgt, tsz, trans);
    combine_kernel<<<1, 128>>>(out);
}